// round 1
// baseline (speedup 1.0000x reference)
#include <cuda_runtime.h>
#include <math.h>

// ---------------------------------------------------------------------------
// Problem constants (LlamaAttention: B=2,S=1024,P=1024,E=2048,H=32,KV=8,HD=64)
// ---------------------------------------------------------------------------
constexpr int B_   = 2;
constexpr int S_   = 1024;
constexpr int P_   = 1024;
constexpr int E_   = 2048;
constexpr int H_   = 32;
constexpr int KV_  = 8;
constexpr int HD_  = 64;
constexpr int G_   = H_ / KV_;        // 4
constexpr int CTX_ = P_ + S_;         // 2048
constexpr int M_   = B_ * S_;         // 2048 rows of tokens

// Scratch (static device allocations are the sanctioned workaround)
__device__ float g_Q[(size_t)M_ * E_];          // 16 MB  (B,S,H,HD) flat
__device__ float g_K[(size_t)M_ * KV_ * HD_];   // 4 MB   (B,S,KV,HD) flat
__device__ float g_V[(size_t)M_ * KV_ * HD_];   // 4 MB
__device__ float g_O[(size_t)M_ * E_];          // 16 MB  (B,S,H,HD) flat

// ---------------------------------------------------------------------------
// SGEMM:  C[m][n] = sum_k A[m][k] * W[n][k]     (A: MxK row-major, W: NxK)
// 128x128 block, BK=8, 256 threads, 8x8 per thread.
// ---------------------------------------------------------------------------
__global__ __launch_bounds__(256) void sgemm_nt(
    const float* __restrict__ A, const float* __restrict__ W,
    float* __restrict__ C, int N, int K)
{
    constexpr int BM = 128, BN = 128, BK = 8;
    __shared__ float As[BK][BM];
    __shared__ float Bs[BK][BN];

    const int tid = threadIdx.x;
    const int bm = blockIdx.y * BM;
    const int bn = blockIdx.x * BN;

    const int lr = tid >> 1;          // 0..127 row within tile
    const int lc = (tid & 1) * 4;     // 0 or 4 (k offset)
    const int tx = tid & 15;          // 0..15
    const int ty = tid >> 4;          // 0..15

    const float* Aptr = A + (size_t)(bm + lr) * K + lc;
    const float* Wptr = W + (size_t)(bn + lr) * K + lc;

    float acc[8][8];
#pragma unroll
    for (int i = 0; i < 8; i++)
#pragma unroll
        for (int j = 0; j < 8; j++) acc[i][j] = 0.f;

    for (int k0 = 0; k0 < K; k0 += BK) {
        float4 av = *(const float4*)(Aptr + k0);
        float4 wv = *(const float4*)(Wptr + k0);
        __syncthreads();
        As[lc + 0][lr] = av.x; As[lc + 1][lr] = av.y;
        As[lc + 2][lr] = av.z; As[lc + 3][lr] = av.w;
        Bs[lc + 0][lr] = wv.x; Bs[lc + 1][lr] = wv.y;
        Bs[lc + 2][lr] = wv.z; Bs[lc + 3][lr] = wv.w;
        __syncthreads();
#pragma unroll
        for (int kk = 0; kk < BK; kk++) {
            float a[8], b[8];
            *(float4*)&a[0] = *(const float4*)&As[kk][ty * 8];
            *(float4*)&a[4] = *(const float4*)&As[kk][ty * 8 + 4];
            *(float4*)&b[0] = *(const float4*)&Bs[kk][tx * 8];
            *(float4*)&b[4] = *(const float4*)&Bs[kk][tx * 8 + 4];
#pragma unroll
            for (int i = 0; i < 8; i++)
#pragma unroll
                for (int j = 0; j < 8; j++)
                    acc[i][j] = fmaf(a[i], b[j], acc[i][j]);
        }
    }

#pragma unroll
    for (int i = 0; i < 8; i++) {
        float* crow = C + (size_t)(bm + ty * 8 + i) * N + bn + tx * 8;
        *(float4*)(crow + 0) = make_float4(acc[i][0], acc[i][1], acc[i][2], acc[i][3]);
        *(float4*)(crow + 4) = make_float4(acc[i][4], acc[i][5], acc[i][6], acc[i][7]);
    }
}

// ---------------------------------------------------------------------------
// RoPE applied in-place to g_Q (H heads) and g_K (KV heads).
// One thread handles dims (d, d+32) of one (token,head).
// ---------------------------------------------------------------------------
__global__ void rope_kernel(const float* __restrict__ cosp,
                            const float* __restrict__ sinp)
{
    int idx = blockIdx.x * blockDim.x + threadIdx.x;
    constexpr int NH = H_ + KV_;                 // 40
    if (idx >= M_ * NH * (HD_ / 2)) return;
    const int d    = idx & 31;
    const int item = idx >> 5;
    const int hh   = item % NH;
    const int row  = item / NH;                  // b*S + s

    const float c1 = cosp[(size_t)row * HD_ + d];
    const float s1 = sinp[(size_t)row * HD_ + d];
    const float c2 = cosp[(size_t)row * HD_ + d + 32];
    const float s2 = sinp[(size_t)row * HD_ + d + 32];

    float* base = (hh < H_)
        ? (g_Q + (size_t)row * E_ + hh * HD_)
        : (g_K + (size_t)row * (KV_ * HD_) + (hh - H_) * HD_);

    const float t1 = base[d];
    const float t2 = base[d + 32];
    base[d]      = t1 * c1 - t2 * s1;
    base[d + 32] = t2 * c2 + t1 * s2;
}

// ---------------------------------------------------------------------------
// Flash attention (fp32, online softmax).
// Grid: (S/64, H, B). 256 threads as 16x16, 4x4 register tile each.
// K tile is stored transposed in smem (KPs[d][key]) -> conflict-free float4
// reads in both mini-GEMMs. KPs is reused to hold P after the score phase.
// Keys t < P come from cache_k/cache_v; t >= P from the freshly projected g_K/g_V.
// ---------------------------------------------------------------------------
constexpr int ATTN_PAD  = 68;   // row stride in floats (16B aligned)
constexpr int ATTN_SMEM = 3 * 64 * ATTN_PAD * 4;

__global__ __launch_bounds__(256) void attn_kernel(
    const float* __restrict__ cache_k, const float* __restrict__ cache_v)
{
    extern __shared__ float sm[];
    float (*Qs) [ATTN_PAD] = (float(*)[ATTN_PAD])(sm);
    float (*KPs)[ATTN_PAD] = (float(*)[ATTN_PAD])(sm + 64 * ATTN_PAD);
    float (*Vs) [ATTN_PAD] = (float(*)[ATTN_PAD])(sm + 2 * 64 * ATTN_PAD);

    const int m0 = blockIdx.x * 64;
    const int h  = blockIdx.y;
    const int b  = blockIdx.z;
    const int kv = h / G_;
    const int tid = threadIdx.x;
    const int tx = tid & 15;
    const int ty = tid >> 4;

    // --- load Q tile (64 rows x 64 dims) ---
    const int ldr = tid >> 2;           // 0..63
    const int ldc = (tid & 3) * 16;     // 0,16,32,48
    {
        const float* src = g_Q + (size_t)(b * S_ + m0 + ldr) * E_ + h * HD_ + ldc;
#pragma unroll
        for (int c4 = 0; c4 < 16; c4 += 4)
            *(float4*)&Qs[ldr][ldc + c4] = *(const float4*)(src + c4);
    }

    float o[4][4];
    float mstate[4], lstate[4];
#pragma unroll
    for (int i = 0; i < 4; i++) {
        mstate[i] = -1e30f; lstate[i] = 0.f;
#pragma unroll
        for (int j = 0; j < 4; j++) o[i][j] = 0.f;
    }

    const int nt = (P_ + m0 + 64) / 64;   // causal: tiles with any valid key

    for (int it = 0; it < nt; ++it) {
        const int t0 = it * 64;
        // --- load K (transposed) and V tiles ---
        const int t = t0 + ldr;
        const float *krow, *vrow;
        if (t < P_) {
            size_t off = ((size_t)(b * KV_ + kv) * CTX_ + t) * HD_;
            krow = cache_k + off;
            vrow = cache_v + off;
        } else {
            size_t off = (size_t)(b * S_ + (t - P_)) * (KV_ * HD_) + kv * HD_;
            krow = g_K + off;
            vrow = g_V + off;
        }
        __syncthreads();    // previous iteration fully done with KPs/Vs
#pragma unroll
        for (int c4 = 0; c4 < 16; c4 += 4) {
            float4 kvv = *(const float4*)(krow + ldc + c4);
            KPs[ldc + c4 + 0][ldr] = kvv.x;
            KPs[ldc + c4 + 1][ldr] = kvv.y;
            KPs[ldc + c4 + 2][ldr] = kvv.z;
            KPs[ldc + c4 + 3][ldr] = kvv.w;
            *(float4*)&Vs[ldr][ldc + c4] = *(const float4*)(vrow + ldc + c4);
        }
        __syncthreads();

        // --- scores: acc[i][j] = sum_d Q[row_i][d] * K[col_j][d] ---
        float acc[4][4];
#pragma unroll
        for (int i = 0; i < 4; i++)
#pragma unroll
            for (int j = 0; j < 4; j++) acc[i][j] = 0.f;

#pragma unroll
        for (int kk = 0; kk < 64; kk += 4) {
            float4 qa[4], kb[4];
#pragma unroll
            for (int i = 0; i < 4; i++) qa[i] = *(const float4*)&Qs[ty * 4 + i][kk];
#pragma unroll
            for (int c = 0; c < 4; c++) kb[c] = *(const float4*)&KPs[kk + c][tx * 4];
#pragma unroll
            for (int i = 0; i < 4; i++) {
                acc[i][0] = fmaf(qa[i].x, kb[0].x, acc[i][0]);
                acc[i][1] = fmaf(qa[i].x, kb[0].y, acc[i][1]);
                acc[i][2] = fmaf(qa[i].x, kb[0].z, acc[i][2]);
                acc[i][3] = fmaf(qa[i].x, kb[0].w, acc[i][3]);
                acc[i][0] = fmaf(qa[i].y, kb[1].x, acc[i][0]);
                acc[i][1] = fmaf(qa[i].y, kb[1].y, acc[i][1]);
                acc[i][2] = fmaf(qa[i].y, kb[1].z, acc[i][2]);
                acc[i][3] = fmaf(qa[i].y, kb[1].w, acc[i][3]);
                acc[i][0] = fmaf(qa[i].z, kb[2].x, acc[i][0]);
                acc[i][1] = fmaf(qa[i].z, kb[2].y, acc[i][1]);
                acc[i][2] = fmaf(qa[i].z, kb[2].z, acc[i][2]);
                acc[i][3] = fmaf(qa[i].z, kb[2].w, acc[i][3]);
                acc[i][0] = fmaf(qa[i].w, kb[3].x, acc[i][0]);
                acc[i][1] = fmaf(qa[i].w, kb[3].y, acc[i][1]);
                acc[i][2] = fmaf(qa[i].w, kb[3].z, acc[i][2]);
                acc[i][3] = fmaf(qa[i].w, kb[3].w, acc[i][3]);
            }
        }

        // --- scale + causal mask ---
#pragma unroll
        for (int i = 0; i < 4; i++) {
            const int qpos = P_ + m0 + ty * 4 + i;
#pragma unroll
            for (int j = 0; j < 4; j++) {
                const int tcol = t0 + tx * 4 + j;
                float v = acc[i][j] * 0.125f;     // 1/sqrt(64)
                acc[i][j] = (tcol > qpos) ? -1e30f : v;
            }
        }

        // --- online softmax (row groups = 16 lanes with the same ty) ---
#pragma unroll
        for (int i = 0; i < 4; i++) {
            float rmax = fmaxf(fmaxf(acc[i][0], acc[i][1]), fmaxf(acc[i][2], acc[i][3]));
#pragma unroll
            for (int off = 8; off > 0; off >>= 1)
                rmax = fmaxf(rmax, __shfl_xor_sync(0xffffffffu, rmax, off));
            const float mnew  = fmaxf(mstate[i], rmax);
            const float alpha = __expf(mstate[i] - mnew);
            float rsum = 0.f;
#pragma unroll
            for (int j = 0; j < 4; j++) {
                const float p = __expf(acc[i][j] - mnew);
                acc[i][j] = p;
                rsum += p;
            }
#pragma unroll
            for (int off = 8; off > 0; off >>= 1)
                rsum += __shfl_xor_sync(0xffffffffu, rsum, off);
            lstate[i] = lstate[i] * alpha + rsum;
            mstate[i] = mnew;
#pragma unroll
            for (int j = 0; j < 4; j++) o[i][j] *= alpha;
        }

        __syncthreads();   // all threads done reading KPs as K
#pragma unroll
        for (int i = 0; i < 4; i++)
            *(float4*)&KPs[ty * 4 + i][tx * 4] =
                make_float4(acc[i][0], acc[i][1], acc[i][2], acc[i][3]);
        __syncthreads();

        // --- o += P @ V ---
#pragma unroll
        for (int kk = 0; kk < 64; kk += 4) {
            float4 pa[4], vb[4];
#pragma unroll
            for (int i = 0; i < 4; i++) pa[i] = *(const float4*)&KPs[ty * 4 + i][kk];
#pragma unroll
            for (int c = 0; c < 4; c++) vb[c] = *(const float4*)&Vs[kk + c][tx * 4];
#pragma unroll
            for (int i = 0; i < 4; i++) {
                o[i][0] = fmaf(pa[i].x, vb[0].x, o[i][0]);
                o[i][1] = fmaf(pa[i].x, vb[0].y, o[i][1]);
                o[i][2] = fmaf(pa[i].x, vb[0].z, o[i][2]);
                o[i][3] = fmaf(pa[i].x, vb[0].w, o[i][3]);
                o[i][0] = fmaf(pa[i].y, vb[1].x, o[i][0]);
                o[i][1] = fmaf(pa[i].y, vb[1].y, o[i][1]);
                o[i][2] = fmaf(pa[i].y, vb[1].z, o[i][2]);
                o[i][3] = fmaf(pa[i].y, vb[1].w, o[i][3]);
                o[i][0] = fmaf(pa[i].z, vb[2].x, o[i][0]);
                o[i][1] = fmaf(pa[i].z, vb[2].y, o[i][1]);
                o[i][2] = fmaf(pa[i].z, vb[2].z, o[i][2]);
                o[i][3] = fmaf(pa[i].z, vb[2].w, o[i][3]);
                o[i][0] = fmaf(pa[i].w, vb[3].x, o[i][0]);
                o[i][1] = fmaf(pa[i].w, vb[3].y, o[i][1]);
                o[i][2] = fmaf(pa[i].w, vb[3].z, o[i][2]);
                o[i][3] = fmaf(pa[i].w, vb[3].w, o[i][3]);
            }
        }
    }

    // --- epilogue: normalize, write O as (B,S,H,HD) ---
#pragma unroll
    for (int i = 0; i < 4; i++) {
        const float inv = 1.f / lstate[i];
        float* dst = g_O + (size_t)(b * S_ + m0 + ty * 4 + i) * E_ + h * HD_ + tx * 4;
        *(float4*)dst = make_float4(o[i][0] * inv, o[i][1] * inv,
                                    o[i][2] * inv, o[i][3] * inv);
    }
}

// ---------------------------------------------------------------------------
// Launcher
// ---------------------------------------------------------------------------
extern "C" void kernel_launch(void* const* d_in, const int* in_sizes, int n_in,
                              void* d_out, int out_size)
{
    const float* x       = (const float*)d_in[0];
    const float* cosp    = (const float*)d_in[1];
    const float* sinp    = (const float*)d_in[2];
    // d_in[3] = mask (causal; computed analytically)
    const float* cache_k = (const float*)d_in[4];
    const float* cache_v = (const float*)d_in[5];
    const float* Wq      = (const float*)d_in[6];
    const float* Wk      = (const float*)d_in[7];
    const float* Wv      = (const float*)d_in[8];
    const float* Wo      = (const float*)d_in[9];
    float* out           = (float*)d_out;

    float *qP, *kP, *vP, *oP;
    cudaGetSymbolAddress((void**)&qP, g_Q);
    cudaGetSymbolAddress((void**)&kP, g_K);
    cudaGetSymbolAddress((void**)&vP, g_V);
    cudaGetSymbolAddress((void**)&oP, g_O);

    cudaFuncSetAttribute(attn_kernel,
                         cudaFuncAttributeMaxDynamicSharedMemorySize, ATTN_SMEM);

    // 1) projections
    sgemm_nt<<<dim3(E_ / 128, M_ / 128), 256>>>(x, Wq, qP, E_, E_);
    sgemm_nt<<<dim3((KV_ * HD_) / 128, M_ / 128), 256>>>(x, Wk, kP, KV_ * HD_, E_);
    sgemm_nt<<<dim3((KV_ * HD_) / 128, M_ / 128), 256>>>(x, Wv, vP, KV_ * HD_, E_);

    // 2) RoPE on Q and K-new
    {
        const int total = M_ * (H_ + KV_) * (HD_ / 2);
        rope_kernel<<<(total + 255) / 256, 256>>>(cosp, sinp);
    }

    // 3) flash attention
    attn_kernel<<<dim3(S_ / 64, H_, B_), 256, ATTN_SMEM>>>(cache_k, cache_v);

    // 4) output projection
    sgemm_nt<<<dim3(E_ / 128, M_ / 128), 256>>>(oP, Wo, out, E_, E_);
}

// round 2
// speedup vs baseline: 1.2738x; 1.2738x over previous
#include <cuda_runtime.h>
#include <math.h>
#include <stdint.h>

// ---------------------------------------------------------------------------
// Problem constants (LlamaAttention: B=2,S=1024,P=1024,E=2048,H=32,KV=8,HD=64)
// ---------------------------------------------------------------------------
constexpr int B_   = 2;
constexpr int S_   = 1024;
constexpr int P_   = 1024;
constexpr int E_   = 2048;
constexpr int H_   = 32;
constexpr int KV_  = 8;
constexpr int HD_  = 64;
constexpr int G_   = H_ / KV_;        // 4
constexpr int CTX_ = P_ + S_;         // 2048
constexpr int M_   = B_ * S_;         // 2048 rows of tokens

// Scratch (static device allocations are the sanctioned workaround)
__device__ float g_Q[(size_t)M_ * E_];          // 16 MB  (B,S,H,HD) flat
__device__ float g_K[(size_t)M_ * KV_ * HD_];   // 4 MB   (B,S,KV,HD) flat
__device__ float g_V[(size_t)M_ * KV_ * HD_];   // 4 MB
__device__ float g_O[(size_t)M_ * E_];          // 16 MB  (B,S,H,HD) flat

// ---------------------------------------------------------------------------
// TF32 helpers: 3xTF32 split  (a = hi + lo, D += hi*hi' + hi*lo' + lo*hi')
// ---------------------------------------------------------------------------
__device__ __forceinline__ void split_tf32(float f, uint32_t& hi, uint32_t& lo)
{
    uint32_t h;
    asm("cvt.rna.tf32.f32 %0, %1;" : "=r"(h) : "f"(f));
    float r = f - __uint_as_float(h);
    uint32_t l;
    asm("cvt.rna.tf32.f32 %0, %1;" : "=r"(l) : "f"(r));
    hi = h; lo = l;
}

__device__ __forceinline__ void mma_tf32(float c[4],
    uint32_t a0, uint32_t a1, uint32_t a2, uint32_t a3,
    uint32_t b0, uint32_t b1)
{
    asm volatile(
        "mma.sync.aligned.m16n8k8.row.col.f32.tf32.tf32.f32 "
        "{%0,%1,%2,%3}, {%4,%5,%6,%7}, {%8,%9}, {%0,%1,%2,%3};"
        : "+f"(c[0]), "+f"(c[1]), "+f"(c[2]), "+f"(c[3])
        : "r"(a0), "r"(a1), "r"(a2), "r"(a3), "r"(b0), "r"(b1));
}

// ---------------------------------------------------------------------------
// TF32 tensor-core GEMM:  C[m][n] = sum_k A[m][k] * W[n][k]
// 128x128 block, BK=32, 256 threads (8 warps as 2x4), warp tile 64x32.
// 3xTF32 split for fp32-grade accuracy.
// ---------------------------------------------------------------------------
__global__ __launch_bounds__(256) void sgemm_tf32(
    const float* __restrict__ A, const float* __restrict__ W,
    float* __restrict__ C, int N, int K)
{
    constexpr int BM = 128, BN = 128, BK = 32;
    constexpr int LDSR = BK + 4;                 // 36 floats per smem row
    __shared__ float As[BM * LDSR];
    __shared__ float Bs[BN * LDSR];

    const int tid  = threadIdx.x;
    const int warp = tid >> 5;
    const int lane = tid & 31;
    const int g    = lane >> 2;        // 0..7
    const int tg   = lane & 3;         // 0..3
    const int wm   = (warp >> 2) * 64; // warp row offset in tile
    const int wn   = (warp & 3) * 32;  // warp col offset in tile

    const int bm = blockIdx.y * BM;
    const int bn = blockIdx.x * BN;

    float acc[4][4][4];                // [mtile][ntile][frag]
#pragma unroll
    for (int i = 0; i < 4; i++)
#pragma unroll
        for (int j = 0; j < 4; j++)
#pragma unroll
            for (int r = 0; r < 4; r++) acc[i][j][r] = 0.f;

    // global->smem staging: each thread loads 16 floats of A, 16 of W
    const int lr = tid >> 1;            // 0..127
    const int lc = (tid & 1) * 16;      // 0 or 16
    const float* Ag = A + (size_t)(bm + lr) * K + lc;
    const float* Wg = W + (size_t)(bn + lr) * K + lc;
    float* AsW = &As[lr * LDSR + lc];
    float* BsW = &Bs[lr * LDSR + lc];

    for (int k0 = 0; k0 < K; k0 += BK) {
        float4 av[4], wv[4];
#pragma unroll
        for (int i = 0; i < 4; i++) {
            av[i] = *(const float4*)(Ag + k0 + i * 4);
            wv[i] = *(const float4*)(Wg + k0 + i * 4);
        }
        __syncthreads();
#pragma unroll
        for (int i = 0; i < 4; i++) {
            *(float4*)(AsW + i * 4) = av[i];
            *(float4*)(BsW + i * 4) = wv[i];
        }
        __syncthreads();

#pragma unroll
        for (int ks = 0; ks < 4; ks++) {
            const int k = ks * 8;
            // --- A fragments (4 m-tiles) ---
            uint32_t ahi[4][4], alo[4][4];
#pragma unroll
            for (int mt = 0; mt < 4; mt++) {
                const int rb = wm + mt * 16;
                float f0 = As[(rb + g)     * LDSR + k + tg];
                float f1 = As[(rb + g + 8) * LDSR + k + tg];
                float f2 = As[(rb + g)     * LDSR + k + tg + 4];
                float f3 = As[(rb + g + 8) * LDSR + k + tg + 4];
                split_tf32(f0, ahi[mt][0], alo[mt][0]);
                split_tf32(f1, ahi[mt][1], alo[mt][1]);
                split_tf32(f2, ahi[mt][2], alo[mt][2]);
                split_tf32(f3, ahi[mt][3], alo[mt][3]);
            }
            // --- B fragments (4 n-tiles) ---
            uint32_t bhi[4][2], blo[4][2];
#pragma unroll
            for (int nt = 0; nt < 4; nt++) {
                const int cb = wn + nt * 8;
                float f0 = Bs[(cb + g) * LDSR + k + tg];
                float f1 = Bs[(cb + g) * LDSR + k + tg + 4];
                split_tf32(f0, bhi[nt][0], blo[nt][0]);
                split_tf32(f1, bhi[nt][1], blo[nt][1]);
            }
            // --- mma: hi*lo + lo*hi + hi*hi ---
#pragma unroll
            for (int mt = 0; mt < 4; mt++) {
#pragma unroll
                for (int nt = 0; nt < 4; nt++) {
                    mma_tf32(acc[mt][nt], ahi[mt][0], ahi[mt][1], ahi[mt][2], ahi[mt][3],
                             blo[nt][0], blo[nt][1]);
                    mma_tf32(acc[mt][nt], alo[mt][0], alo[mt][1], alo[mt][2], alo[mt][3],
                             bhi[nt][0], bhi[nt][1]);
                    mma_tf32(acc[mt][nt], ahi[mt][0], ahi[mt][1], ahi[mt][2], ahi[mt][3],
                             bhi[nt][0], bhi[nt][1]);
                }
            }
        }
    }

    // epilogue
#pragma unroll
    for (int mt = 0; mt < 4; mt++) {
#pragma unroll
        for (int nt = 0; nt < 4; nt++) {
            const int row0 = bm + wm + mt * 16 + g;
            const int col  = bn + wn + nt * 8 + 2 * tg;
            *(float2*)&C[(size_t)row0 * N + col] =
                make_float2(acc[mt][nt][0], acc[mt][nt][1]);
            *(float2*)&C[(size_t)(row0 + 8) * N + col] =
                make_float2(acc[mt][nt][2], acc[mt][nt][3]);
        }
    }
}

// ---------------------------------------------------------------------------
// RoPE applied in-place to g_Q (H heads) and g_K (KV heads).
// ---------------------------------------------------------------------------
__global__ void rope_kernel(const float* __restrict__ cosp,
                            const float* __restrict__ sinp)
{
    int idx = blockIdx.x * blockDim.x + threadIdx.x;
    constexpr int NH = H_ + KV_;                 // 40
    if (idx >= M_ * NH * (HD_ / 2)) return;
    const int d    = idx & 31;
    const int item = idx >> 5;
    const int hh   = item % NH;
    const int row  = item / NH;                  // b*S + s

    const float c1 = cosp[(size_t)row * HD_ + d];
    const float s1 = sinp[(size_t)row * HD_ + d];
    const float c2 = cosp[(size_t)row * HD_ + d + 32];
    const float s2 = sinp[(size_t)row * HD_ + d + 32];

    float* base = (hh < H_)
        ? (g_Q + (size_t)row * E_ + hh * HD_)
        : (g_K + (size_t)row * (KV_ * HD_) + (hh - H_) * HD_);

    const float t1 = base[d];
    const float t2 = base[d + 32];
    base[d]      = t1 * c1 - t2 * s1;
    base[d + 32] = t2 * c2 + t1 * s2;
}

// ---------------------------------------------------------------------------
// Flash attention (fp32, online softmax). Same as R0 (known correct).
// ---------------------------------------------------------------------------
constexpr int ATTN_PAD  = 68;   // row stride in floats (16B aligned)
constexpr int ATTN_SMEM = 3 * 64 * ATTN_PAD * 4;

__global__ __launch_bounds__(256) void attn_kernel(
    const float* __restrict__ cache_k, const float* __restrict__ cache_v)
{
    extern __shared__ float sm[];
    float (*Qs) [ATTN_PAD] = (float(*)[ATTN_PAD])(sm);
    float (*KPs)[ATTN_PAD] = (float(*)[ATTN_PAD])(sm + 64 * ATTN_PAD);
    float (*Vs) [ATTN_PAD] = (float(*)[ATTN_PAD])(sm + 2 * 64 * ATTN_PAD);

    const int m0 = blockIdx.x * 64;
    const int h  = blockIdx.y;
    const int b  = blockIdx.z;
    const int kv = h / G_;
    const int tid = threadIdx.x;
    const int tx = tid & 15;
    const int ty = tid >> 4;

    const int ldr = tid >> 2;           // 0..63
    const int ldc = (tid & 3) * 16;     // 0,16,32,48
    {
        const float* src = g_Q + (size_t)(b * S_ + m0 + ldr) * E_ + h * HD_ + ldc;
#pragma unroll
        for (int c4 = 0; c4 < 16; c4 += 4)
            *(float4*)&Qs[ldr][ldc + c4] = *(const float4*)(src + c4);
    }

    float o[4][4];
    float mstate[4], lstate[4];
#pragma unroll
    for (int i = 0; i < 4; i++) {
        mstate[i] = -1e30f; lstate[i] = 0.f;
#pragma unroll
        for (int j = 0; j < 4; j++) o[i][j] = 0.f;
    }

    const int nt = (P_ + m0 + 64) / 64;   // causal: tiles with any valid key

    for (int it = 0; it < nt; ++it) {
        const int t0 = it * 64;
        const int t = t0 + ldr;
        const float *krow, *vrow;
        if (t < P_) {
            size_t off = ((size_t)(b * KV_ + kv) * CTX_ + t) * HD_;
            krow = cache_k + off;
            vrow = cache_v + off;
        } else {
            size_t off = (size_t)(b * S_ + (t - P_)) * (KV_ * HD_) + kv * HD_;
            krow = g_K + off;
            vrow = g_V + off;
        }
        __syncthreads();
#pragma unroll
        for (int c4 = 0; c4 < 16; c4 += 4) {
            float4 kvv = *(const float4*)(krow + ldc + c4);
            KPs[ldc + c4 + 0][ldr] = kvv.x;
            KPs[ldc + c4 + 1][ldr] = kvv.y;
            KPs[ldc + c4 + 2][ldr] = kvv.z;
            KPs[ldc + c4 + 3][ldr] = kvv.w;
            *(float4*)&Vs[ldr][ldc + c4] = *(const float4*)(vrow + ldc + c4);
        }
        __syncthreads();

        float acc[4][4];
#pragma unroll
        for (int i = 0; i < 4; i++)
#pragma unroll
            for (int j = 0; j < 4; j++) acc[i][j] = 0.f;

#pragma unroll
        for (int kk = 0; kk < 64; kk += 4) {
            float4 qa[4], kb[4];
#pragma unroll
            for (int i = 0; i < 4; i++) qa[i] = *(const float4*)&Qs[ty * 4 + i][kk];
#pragma unroll
            for (int c = 0; c < 4; c++) kb[c] = *(const float4*)&KPs[kk + c][tx * 4];
#pragma unroll
            for (int i = 0; i < 4; i++) {
                acc[i][0] = fmaf(qa[i].x, kb[0].x, acc[i][0]);
                acc[i][1] = fmaf(qa[i].x, kb[0].y, acc[i][1]);
                acc[i][2] = fmaf(qa[i].x, kb[0].z, acc[i][2]);
                acc[i][3] = fmaf(qa[i].x, kb[0].w, acc[i][3]);
                acc[i][0] = fmaf(qa[i].y, kb[1].x, acc[i][0]);
                acc[i][1] = fmaf(qa[i].y, kb[1].y, acc[i][1]);
                acc[i][2] = fmaf(qa[i].y, kb[1].z, acc[i][2]);
                acc[i][3] = fmaf(qa[i].y, kb[1].w, acc[i][3]);
                acc[i][0] = fmaf(qa[i].z, kb[2].x, acc[i][0]);
                acc[i][1] = fmaf(qa[i].z, kb[2].y, acc[i][1]);
                acc[i][2] = fmaf(qa[i].z, kb[2].z, acc[i][2]);
                acc[i][3] = fmaf(qa[i].z, kb[2].w, acc[i][3]);
                acc[i][0] = fmaf(qa[i].w, kb[3].x, acc[i][0]);
                acc[i][1] = fmaf(qa[i].w, kb[3].y, acc[i][1]);
                acc[i][2] = fmaf(qa[i].w, kb[3].z, acc[i][2]);
                acc[i][3] = fmaf(qa[i].w, kb[3].w, acc[i][3]);
            }
        }

#pragma unroll
        for (int i = 0; i < 4; i++) {
            const int qpos = P_ + m0 + ty * 4 + i;
#pragma unroll
            for (int j = 0; j < 4; j++) {
                const int tcol = t0 + tx * 4 + j;
                float v = acc[i][j] * 0.125f;     // 1/sqrt(64)
                acc[i][j] = (tcol > qpos) ? -1e30f : v;
            }
        }

#pragma unroll
        for (int i = 0; i < 4; i++) {
            float rmax = fmaxf(fmaxf(acc[i][0], acc[i][1]), fmaxf(acc[i][2], acc[i][3]));
#pragma unroll
            for (int off = 8; off > 0; off >>= 1)
                rmax = fmaxf(rmax, __shfl_xor_sync(0xffffffffu, rmax, off));
            const float mnew  = fmaxf(mstate[i], rmax);
            const float alpha = __expf(mstate[i] - mnew);
            float rsum = 0.f;
#pragma unroll
            for (int j = 0; j < 4; j++) {
                const float p = __expf(acc[i][j] - mnew);
                acc[i][j] = p;
                rsum += p;
            }
#pragma unroll
            for (int off = 8; off > 0; off >>= 1)
                rsum += __shfl_xor_sync(0xffffffffu, rsum, off);
            lstate[i] = lstate[i] * alpha + rsum;
            mstate[i] = mnew;
#pragma unroll
            for (int j = 0; j < 4; j++) o[i][j] *= alpha;
        }

        __syncthreads();
#pragma unroll
        for (int i = 0; i < 4; i++)
            *(float4*)&KPs[ty * 4 + i][tx * 4] =
                make_float4(acc[i][0], acc[i][1], acc[i][2], acc[i][3]);
        __syncthreads();

#pragma unroll
        for (int kk = 0; kk < 64; kk += 4) {
            float4 pa[4], vb[4];
#pragma unroll
            for (int i = 0; i < 4; i++) pa[i] = *(const float4*)&KPs[ty * 4 + i][kk];
#pragma unroll
            for (int c = 0; c < 4; c++) vb[c] = *(const float4*)&Vs[kk + c][tx * 4];
#pragma unroll
            for (int i = 0; i < 4; i++) {
                o[i][0] = fmaf(pa[i].x, vb[0].x, o[i][0]);
                o[i][1] = fmaf(pa[i].x, vb[0].y, o[i][1]);
                o[i][2] = fmaf(pa[i].x, vb[0].z, o[i][2]);
                o[i][3] = fmaf(pa[i].x, vb[0].w, o[i][3]);
                o[i][0] = fmaf(pa[i].y, vb[1].x, o[i][0]);
                o[i][1] = fmaf(pa[i].y, vb[1].y, o[i][1]);
                o[i][2] = fmaf(pa[i].y, vb[1].z, o[i][2]);
                o[i][3] = fmaf(pa[i].y, vb[1].w, o[i][3]);
                o[i][0] = fmaf(pa[i].z, vb[2].x, o[i][0]);
                o[i][1] = fmaf(pa[i].z, vb[2].y, o[i][1]);
                o[i][2] = fmaf(pa[i].z, vb[2].z, o[i][2]);
                o[i][3] = fmaf(pa[i].z, vb[2].w, o[i][3]);
                o[i][0] = fmaf(pa[i].w, vb[3].x, o[i][0]);
                o[i][1] = fmaf(pa[i].w, vb[3].y, o[i][1]);
                o[i][2] = fmaf(pa[i].w, vb[3].z, o[i][2]);
                o[i][3] = fmaf(pa[i].w, vb[3].w, o[i][3]);
            }
        }
    }

#pragma unroll
    for (int i = 0; i < 4; i++) {
        const float inv = 1.f / lstate[i];
        float* dst = g_O + (size_t)(b * S_ + m0 + ty * 4 + i) * E_ + h * HD_ + tx * 4;
        *(float4*)dst = make_float4(o[i][0] * inv, o[i][1] * inv,
                                    o[i][2] * inv, o[i][3] * inv);
    }
}

// ---------------------------------------------------------------------------
// Launcher
// ---------------------------------------------------------------------------
extern "C" void kernel_launch(void* const* d_in, const int* in_sizes, int n_in,
                              void* d_out, int out_size)
{
    const float* x       = (const float*)d_in[0];
    const float* cosp    = (const float*)d_in[1];
    const float* sinp    = (const float*)d_in[2];
    // d_in[3] = mask (causal; computed analytically)
    const float* cache_k = (const float*)d_in[4];
    const float* cache_v = (const float*)d_in[5];
    const float* Wq      = (const float*)d_in[6];
    const float* Wk      = (const float*)d_in[7];
    const float* Wv      = (const float*)d_in[8];
    const float* Wo      = (const float*)d_in[9];
    float* out           = (float*)d_out;

    float *qP, *kP, *vP, *oP;
    cudaGetSymbolAddress((void**)&qP, g_Q);
    cudaGetSymbolAddress((void**)&kP, g_K);
    cudaGetSymbolAddress((void**)&vP, g_V);
    cudaGetSymbolAddress((void**)&oP, g_O);

    cudaFuncSetAttribute(attn_kernel,
                         cudaFuncAttributeMaxDynamicSharedMemorySize, ATTN_SMEM);

    // 1) projections (TF32 tensor cores, 3x split)
    sgemm_tf32<<<dim3(E_ / 128, M_ / 128), 256>>>(x, Wq, qP, E_, E_);
    sgemm_tf32<<<dim3((KV_ * HD_) / 128, M_ / 128), 256>>>(x, Wk, kP, KV_ * HD_, E_);
    sgemm_tf32<<<dim3((KV_ * HD_) / 128, M_ / 128), 256>>>(x, Wv, vP, KV_ * HD_, E_);

    // 2) RoPE on Q and K-new
    {
        const int total = M_ * (H_ + KV_) * (HD_ / 2);
        rope_kernel<<<(total + 255) / 256, 256>>>(cosp, sinp);
    }

    // 3) flash attention
    attn_kernel<<<dim3(S_ / 64, H_, B_), 256, ATTN_SMEM>>>(cache_k, cache_v);

    // 4) output projection
    sgemm_tf32<<<dim3(E_ / 128, M_ / 128), 256>>>(oP, Wo, out, E_, E_);
}

// round 3
// speedup vs baseline: 1.6854x; 1.3231x over previous
#include <cuda_runtime.h>
#include <cuda_bf16.h>
#include <math.h>
#include <stdint.h>

// ---------------------------------------------------------------------------
// Problem constants (LlamaAttention: B=2,S=1024,P=1024,E=2048,H=32,KV=8,HD=64)
// ---------------------------------------------------------------------------
constexpr int B_   = 2;
constexpr int S_   = 1024;
constexpr int P_   = 1024;
constexpr int E_   = 2048;
constexpr int H_   = 32;
constexpr int KV_  = 8;
constexpr int HD_  = 64;
constexpr int G_   = H_ / KV_;        // 4
constexpr int CTX_ = P_ + S_;         // 2048
constexpr int M_   = B_ * S_;         // 2048 rows of tokens

// Scratch (static device allocations are the sanctioned workaround)
__device__ float g_Q[(size_t)M_ * E_];          // 16 MB  (B,S,H,HD) flat
__device__ float g_K[(size_t)M_ * KV_ * HD_];   // 4 MB   (B,S,KV,HD) flat
__device__ float g_V[(size_t)M_ * KV_ * HD_];   // 4 MB
__device__ float g_O[(size_t)M_ * E_];          // 16 MB  (B,S,H,HD) flat

// ---------------------------------------------------------------------------
// bf16x3 (Ootomo) helpers
// ---------------------------------------------------------------------------
__device__ __forceinline__ uint2 split2(float a, float b)
{
    __nv_bfloat162 h = __floats2bfloat162_rn(a, b);
    float ra = a - __low2float(h);
    float rb = b - __high2float(h);
    __nv_bfloat162 l = __floats2bfloat162_rn(ra, rb);
    uint2 r;
    r.x = *reinterpret_cast<uint32_t*>(&h);
    r.y = *reinterpret_cast<uint32_t*>(&l);
    return r;
}

__device__ __forceinline__ void mma_bf16(float c[4],
    uint32_t a0, uint32_t a1, uint32_t a2, uint32_t a3,
    uint32_t b0, uint32_t b1)
{
    asm volatile(
        "mma.sync.aligned.m16n8k16.row.col.f32.bf16.bf16.f32 "
        "{%0,%1,%2,%3}, {%4,%5,%6,%7}, {%8,%9}, {%0,%1,%2,%3};"
        : "+f"(c[0]), "+f"(c[1]), "+f"(c[2]), "+f"(c[3])
        : "r"(a0), "r"(a1), "r"(a2), "r"(a3), "r"(b0), "r"(b1));
}

// ---------------------------------------------------------------------------
// bf16x3 tensor-core GEMM core: C[m][n] = sum_k A[m][k] * W[n][k]
// 128x128 block, BK=32, 256 threads (8 warps as 2x4), warp tile 64x32.
// smem holds pre-split (hi,lo) bf16x2 pairs -> mainloop is pure LDS.64 + HMMA.
// ---------------------------------------------------------------------------
constexpr int GSTR = 20;   // smem row stride in uint2 (16 pairs + pad 4)

struct SmemGemm {
    uint2 Ap[128 * GSTR];
    uint2 Bp[128 * GSTR];
};

__device__ __forceinline__ void gemm_core(
    const float* __restrict__ A, const float* __restrict__ W,
    float* __restrict__ C, int N, int K, int bm, int bn, SmemGemm* sm)
{
    constexpr int BK = 32;
    const int tid  = threadIdx.x;
    const int warp = tid >> 5;
    const int lane = tid & 31;
    const int g    = lane >> 2;        // 0..7
    const int tg   = lane & 3;         // 0..3
    const int wm   = (warp >> 2) * 64;
    const int wn   = (warp & 3) * 32;

    float acc[4][4][4];
#pragma unroll
    for (int i = 0; i < 4; i++)
#pragma unroll
        for (int j = 0; j < 4; j++)
#pragma unroll
            for (int r = 0; r < 4; r++) acc[i][j][r] = 0.f;

    // staging: each thread loads 16 floats of A row and 16 of W row
    const int lr = tid >> 1;            // 0..127
    const int pc = (tid & 1) * 8;       // pair offset 0 or 8
    const float* Ag = A + (size_t)(bm + lr) * K + pc * 2;
    const float* Wg = W + (size_t)(bn + lr) * K + pc * 2;
    uint2* AsW = &sm->Ap[lr * GSTR + pc];
    uint2* BsW = &sm->Bp[lr * GSTR + pc];

    for (int k0 = 0; k0 < K; k0 += BK) {
        float4 av[4], wv[4];
#pragma unroll
        for (int i = 0; i < 4; i++) {
            av[i] = *(const float4*)(Ag + k0 + i * 4);
            wv[i] = *(const float4*)(Wg + k0 + i * 4);
        }
        __syncthreads();
#pragma unroll
        for (int i = 0; i < 4; i++) {
            AsW[i * 2 + 0] = split2(av[i].x, av[i].y);
            AsW[i * 2 + 1] = split2(av[i].z, av[i].w);
            BsW[i * 2 + 0] = split2(wv[i].x, wv[i].y);
            BsW[i * 2 + 1] = split2(wv[i].z, wv[i].w);
        }
        __syncthreads();

#pragma unroll
        for (int ks = 0; ks < 2; ks++) {
            const int kp = ks * 8;       // pair offset of this k16 step
            uint2 ta[4][4];
#pragma unroll
            for (int mt = 0; mt < 4; mt++) {
                const int rb = wm + mt * 16;
                ta[mt][0] = sm->Ap[(rb + g)     * GSTR + kp + tg];
                ta[mt][1] = sm->Ap[(rb + g + 8) * GSTR + kp + tg];
                ta[mt][2] = sm->Ap[(rb + g)     * GSTR + kp + tg + 4];
                ta[mt][3] = sm->Ap[(rb + g + 8) * GSTR + kp + tg + 4];
            }
            uint2 tb[4][2];
#pragma unroll
            for (int nt = 0; nt < 4; nt++) {
                const int cb = wn + nt * 8;
                tb[nt][0] = sm->Bp[(cb + g) * GSTR + kp + tg];
                tb[nt][1] = sm->Bp[(cb + g) * GSTR + kp + tg + 4];
            }
#pragma unroll
            for (int mt = 0; mt < 4; mt++) {
#pragma unroll
                for (int nt = 0; nt < 4; nt++) {
                    // hi*lo + lo*hi + hi*hi
                    mma_bf16(acc[mt][nt],
                             ta[mt][0].x, ta[mt][1].x, ta[mt][2].x, ta[mt][3].x,
                             tb[nt][0].y, tb[nt][1].y);
                    mma_bf16(acc[mt][nt],
                             ta[mt][0].y, ta[mt][1].y, ta[mt][2].y, ta[mt][3].y,
                             tb[nt][0].x, tb[nt][1].x);
                    mma_bf16(acc[mt][nt],
                             ta[mt][0].x, ta[mt][1].x, ta[mt][2].x, ta[mt][3].x,
                             tb[nt][0].x, tb[nt][1].x);
                }
            }
        }
    }

    // epilogue
#pragma unroll
    for (int mt = 0; mt < 4; mt++) {
#pragma unroll
        for (int nt = 0; nt < 4; nt++) {
            const int row0 = bm + wm + mt * 16 + g;
            const int col  = bn + wn + nt * 8 + 2 * tg;
            *(float2*)&C[(size_t)row0 * N + col] =
                make_float2(acc[mt][nt][0], acc[mt][nt][1]);
            *(float2*)&C[(size_t)(row0 + 8) * N + col] =
                make_float2(acc[mt][nt][2], acc[mt][nt][3]);
        }
    }
}

__global__ __launch_bounds__(256) void sgemm_bf16(
    const float* __restrict__ A, const float* __restrict__ W,
    float* __restrict__ C, int N, int K)
{
    __shared__ SmemGemm sm;
    gemm_core(A, W, C, N, K, blockIdx.y * 128, blockIdx.x * 128, &sm);
}

// Fused K+V projection: grid.x = 8 (4 blocks K, 4 blocks V), one full wave.
__global__ __launch_bounds__(256) void sgemm_bf16_kv(
    const float* __restrict__ A,
    const float* __restrict__ Wk, const float* __restrict__ Wv,
    float* __restrict__ Ck, float* __restrict__ Cv, int K)
{
    __shared__ SmemGemm sm;
    const int bx = blockIdx.x;
    const float* W = (bx < 4) ? Wk : Wv;
    float* C       = (bx < 4) ? Ck : Cv;
    gemm_core(A, W, C, KV_ * HD_, K, blockIdx.y * 128, (bx & 3) * 128, &sm);
}

// ---------------------------------------------------------------------------
// RoPE applied in-place to g_Q (H heads) and g_K (KV heads).
// ---------------------------------------------------------------------------
__global__ void rope_kernel(const float* __restrict__ cosp,
                            const float* __restrict__ sinp)
{
    int idx = blockIdx.x * blockDim.x + threadIdx.x;
    constexpr int NH = H_ + KV_;                 // 40
    if (idx >= M_ * NH * (HD_ / 2)) return;
    const int d    = idx & 31;
    const int item = idx >> 5;
    const int hh   = item % NH;
    const int row  = item / NH;                  // b*S + s

    const float c1 = cosp[(size_t)row * HD_ + d];
    const float s1 = sinp[(size_t)row * HD_ + d];
    const float c2 = cosp[(size_t)row * HD_ + d + 32];
    const float s2 = sinp[(size_t)row * HD_ + d + 32];

    float* base = (hh < H_)
        ? (g_Q + (size_t)row * E_ + hh * HD_)
        : (g_K + (size_t)row * (KV_ * HD_) + (hh - H_) * HD_);

    const float t1 = base[d];
    const float t2 = base[d + 32];
    base[d]      = t1 * c1 - t2 * s1;
    base[d + 32] = t2 * c2 + t1 * s2;
}

// ---------------------------------------------------------------------------
// Flash attention (fp32, online softmax). Known correct (R0/R1).
// ---------------------------------------------------------------------------
constexpr int ATTN_PAD  = 68;   // row stride in floats (16B aligned)
constexpr int ATTN_SMEM = 3 * 64 * ATTN_PAD * 4;

__global__ __launch_bounds__(256) void attn_kernel(
    const float* __restrict__ cache_k, const float* __restrict__ cache_v)
{
    extern __shared__ float sm[];
    float (*Qs) [ATTN_PAD] = (float(*)[ATTN_PAD])(sm);
    float (*KPs)[ATTN_PAD] = (float(*)[ATTN_PAD])(sm + 64 * ATTN_PAD);
    float (*Vs) [ATTN_PAD] = (float(*)[ATTN_PAD])(sm + 2 * 64 * ATTN_PAD);

    const int m0 = blockIdx.x * 64;
    const int h  = blockIdx.y;
    const int b  = blockIdx.z;
    const int kv = h / G_;
    const int tid = threadIdx.x;
    const int tx = tid & 15;
    const int ty = tid >> 4;

    const int ldr = tid >> 2;           // 0..63
    const int ldc = (tid & 3) * 16;     // 0,16,32,48
    {
        const float* src = g_Q + (size_t)(b * S_ + m0 + ldr) * E_ + h * HD_ + ldc;
#pragma unroll
        for (int c4 = 0; c4 < 16; c4 += 4)
            *(float4*)&Qs[ldr][ldc + c4] = *(const float4*)(src + c4);
    }

    float o[4][4];
    float mstate[4], lstate[4];
#pragma unroll
    for (int i = 0; i < 4; i++) {
        mstate[i] = -1e30f; lstate[i] = 0.f;
#pragma unroll
        for (int j = 0; j < 4; j++) o[i][j] = 0.f;
    }

    const int nt = (P_ + m0 + 64) / 64;   // causal: tiles with any valid key

    for (int it = 0; it < nt; ++it) {
        const int t0 = it * 64;
        const int t = t0 + ldr;
        const float *krow, *vrow;
        if (t < P_) {
            size_t off = ((size_t)(b * KV_ + kv) * CTX_ + t) * HD_;
            krow = cache_k + off;
            vrow = cache_v + off;
        } else {
            size_t off = (size_t)(b * S_ + (t - P_)) * (KV_ * HD_) + kv * HD_;
            krow = g_K + off;
            vrow = g_V + off;
        }
        __syncthreads();
#pragma unroll
        for (int c4 = 0; c4 < 16; c4 += 4) {
            float4 kvv = *(const float4*)(krow + ldc + c4);
            KPs[ldc + c4 + 0][ldr] = kvv.x;
            KPs[ldc + c4 + 1][ldr] = kvv.y;
            KPs[ldc + c4 + 2][ldr] = kvv.z;
            KPs[ldc + c4 + 3][ldr] = kvv.w;
            *(float4*)&Vs[ldr][ldc + c4] = *(const float4*)(vrow + ldc + c4);
        }
        __syncthreads();

        float acc[4][4];
#pragma unroll
        for (int i = 0; i < 4; i++)
#pragma unroll
            for (int j = 0; j < 4; j++) acc[i][j] = 0.f;

#pragma unroll
        for (int kk = 0; kk < 64; kk += 4) {
            float4 qa[4], kb[4];
#pragma unroll
            for (int i = 0; i < 4; i++) qa[i] = *(const float4*)&Qs[ty * 4 + i][kk];
#pragma unroll
            for (int c = 0; c < 4; c++) kb[c] = *(const float4*)&KPs[kk + c][tx * 4];
#pragma unroll
            for (int i = 0; i < 4; i++) {
                acc[i][0] = fmaf(qa[i].x, kb[0].x, acc[i][0]);
                acc[i][1] = fmaf(qa[i].x, kb[0].y, acc[i][1]);
                acc[i][2] = fmaf(qa[i].x, kb[0].z, acc[i][2]);
                acc[i][3] = fmaf(qa[i].x, kb[0].w, acc[i][3]);
                acc[i][0] = fmaf(qa[i].y, kb[1].x, acc[i][0]);
                acc[i][1] = fmaf(qa[i].y, kb[1].y, acc[i][1]);
                acc[i][2] = fmaf(qa[i].y, kb[1].z, acc[i][2]);
                acc[i][3] = fmaf(qa[i].y, kb[1].w, acc[i][3]);
                acc[i][0] = fmaf(qa[i].z, kb[2].x, acc[i][0]);
                acc[i][1] = fmaf(qa[i].z, kb[2].y, acc[i][1]);
                acc[i][2] = fmaf(qa[i].z, kb[2].z, acc[i][2]);
                acc[i][3] = fmaf(qa[i].z, kb[2].w, acc[i][3]);
                acc[i][0] = fmaf(qa[i].w, kb[3].x, acc[i][0]);
                acc[i][1] = fmaf(qa[i].w, kb[3].y, acc[i][1]);
                acc[i][2] = fmaf(qa[i].w, kb[3].z, acc[i][2]);
                acc[i][3] = fmaf(qa[i].w, kb[3].w, acc[i][3]);
            }
        }

#pragma unroll
        for (int i = 0; i < 4; i++) {
            const int qpos = P_ + m0 + ty * 4 + i;
#pragma unroll
            for (int j = 0; j < 4; j++) {
                const int tcol = t0 + tx * 4 + j;
                float v = acc[i][j] * 0.125f;     // 1/sqrt(64)
                acc[i][j] = (tcol > qpos) ? -1e30f : v;
            }
        }

#pragma unroll
        for (int i = 0; i < 4; i++) {
            float rmax = fmaxf(fmaxf(acc[i][0], acc[i][1]), fmaxf(acc[i][2], acc[i][3]));
#pragma unroll
            for (int off = 8; off > 0; off >>= 1)
                rmax = fmaxf(rmax, __shfl_xor_sync(0xffffffffu, rmax, off));
            const float mnew  = fmaxf(mstate[i], rmax);
            const float alpha = __expf(mstate[i] - mnew);
            float rsum = 0.f;
#pragma unroll
            for (int j = 0; j < 4; j++) {
                const float p = __expf(acc[i][j] - mnew);
                acc[i][j] = p;
                rsum += p;
            }
#pragma unroll
            for (int off = 8; off > 0; off >>= 1)
                rsum += __shfl_xor_sync(0xffffffffu, rsum, off);
            lstate[i] = lstate[i] * alpha + rsum;
            mstate[i] = mnew;
#pragma unroll
            for (int j = 0; j < 4; j++) o[i][j] *= alpha;
        }

        __syncthreads();
#pragma unroll
        for (int i = 0; i < 4; i++)
            *(float4*)&KPs[ty * 4 + i][tx * 4] =
                make_float4(acc[i][0], acc[i][1], acc[i][2], acc[i][3]);
        __syncthreads();

#pragma unroll
        for (int kk = 0; kk < 64; kk += 4) {
            float4 pa[4], vb[4];
#pragma unroll
            for (int i = 0; i < 4; i++) pa[i] = *(const float4*)&KPs[ty * 4 + i][kk];
#pragma unroll
            for (int c = 0; c < 4; c++) vb[c] = *(const float4*)&Vs[kk + c][tx * 4];
#pragma unroll
            for (int i = 0; i < 4; i++) {
                o[i][0] = fmaf(pa[i].x, vb[0].x, o[i][0]);
                o[i][1] = fmaf(pa[i].x, vb[0].y, o[i][1]);
                o[i][2] = fmaf(pa[i].x, vb[0].z, o[i][2]);
                o[i][3] = fmaf(pa[i].x, vb[0].w, o[i][3]);
                o[i][0] = fmaf(pa[i].y, vb[1].x, o[i][0]);
                o[i][1] = fmaf(pa[i].y, vb[1].y, o[i][1]);
                o[i][2] = fmaf(pa[i].y, vb[1].z, o[i][2]);
                o[i][3] = fmaf(pa[i].y, vb[1].w, o[i][3]);
                o[i][0] = fmaf(pa[i].z, vb[2].x, o[i][0]);
                o[i][1] = fmaf(pa[i].z, vb[2].y, o[i][1]);
                o[i][2] = fmaf(pa[i].z, vb[2].z, o[i][2]);
                o[i][3] = fmaf(pa[i].z, vb[2].w, o[i][3]);
                o[i][0] = fmaf(pa[i].w, vb[3].x, o[i][0]);
                o[i][1] = fmaf(pa[i].w, vb[3].y, o[i][1]);
                o[i][2] = fmaf(pa[i].w, vb[3].z, o[i][2]);
                o[i][3] = fmaf(pa[i].w, vb[3].w, o[i][3]);
            }
        }
    }

#pragma unroll
    for (int i = 0; i < 4; i++) {
        const float inv = 1.f / lstate[i];
        float* dst = g_O + (size_t)(b * S_ + m0 + ty * 4 + i) * E_ + h * HD_ + tx * 4;
        *(float4*)dst = make_float4(o[i][0] * inv, o[i][1] * inv,
                                    o[i][2] * inv, o[i][3] * inv);
    }
}

// ---------------------------------------------------------------------------
// Launcher
// ---------------------------------------------------------------------------
extern "C" void kernel_launch(void* const* d_in, const int* in_sizes, int n_in,
                              void* d_out, int out_size)
{
    const float* x       = (const float*)d_in[0];
    const float* cosp    = (const float*)d_in[1];
    const float* sinp    = (const float*)d_in[2];
    // d_in[3] = mask (causal; computed analytically)
    const float* cache_k = (const float*)d_in[4];
    const float* cache_v = (const float*)d_in[5];
    const float* Wq      = (const float*)d_in[6];
    const float* Wk      = (const float*)d_in[7];
    const float* Wv      = (const float*)d_in[8];
    const float* Wo      = (const float*)d_in[9];
    float* out           = (float*)d_out;

    float *qP, *kP, *vP, *oP;
    cudaGetSymbolAddress((void**)&qP, g_Q);
    cudaGetSymbolAddress((void**)&kP, g_K);
    cudaGetSymbolAddress((void**)&vP, g_V);
    cudaGetSymbolAddress((void**)&oP, g_O);

    cudaFuncSetAttribute(attn_kernel,
                         cudaFuncAttributeMaxDynamicSharedMemorySize, ATTN_SMEM);

    // 1) projections (bf16x3 tensor cores)
    sgemm_bf16<<<dim3(E_ / 128, M_ / 128), 256>>>(x, Wq, qP, E_, E_);
    sgemm_bf16_kv<<<dim3(8, M_ / 128), 256>>>(x, Wk, Wv, kP, vP, E_);

    // 2) RoPE on Q and K-new
    {
        const int total = M_ * (H_ + KV_) * (HD_ / 2);
        rope_kernel<<<(total + 255) / 256, 256>>>(cosp, sinp);
    }

    // 3) flash attention
    attn_kernel<<<dim3(S_ / 64, H_, B_), 256, ATTN_SMEM>>>(cache_k, cache_v);

    // 4) output projection
    sgemm_bf16<<<dim3(E_ / 128, M_ / 128), 256>>>(oP, Wo, out, E_, E_);
}